// round 15
// baseline (speedup 1.0000x reference)
#include <cuda_runtime.h>
#include <cuda_bf16.h>
#include <cstdint>

// ExpertCapacityBuffer: N tokens, TOP_K=2, 64 experts.
// capacity = ceil(1.25*N*2/64). Flat slot-major: f = slot*N + tok.
// rank(f) = #{g<f : expert(g)==expert(f)}; keep iff rank < capacity.
//
// Overflow shortcut: expert e drops anything iff total(e) > capacity.
// NO grid barrier: every block writes speculative-final outputs + histogram
// + totals, then exits. The LAST-arriving block checks g_tot; if some expert
// overflows (cold path) it alone re-sweeps all tiles in flat order with
// running offsets and overwrites weights+mask exactly. Indices are always
// correct as speculated.

#define NE   64
#define NEP  65              // padded row kills smem bank conflicts
#define TPB  1024
#define EPT  1024
#define MAXROWS 4096

__device__ int g_cnt[MAXROWS][NE];
__device__ int g_tot[NE];    // zero at start; reset by last block
__device__ int g_done = 0;

// warp-0 dtype probe: int64 values <64 => odd 32-bit words of first 256B zero.
__device__ __forceinline__ void probe_w0(const void* eraw, int lane, int* s_is64) {
    if (threadIdx.x < 32) {
        unsigned x = ((const unsigned*)eraw)[2 * lane + 1];
        unsigned nz = __ballot_sync(0xFFFFFFFFu, x != 0u);
        if (lane == 0) *s_is64 = (nz == 0u);
    }
}

__global__ void __launch_bounds__(TPB, 1)
k_fused(const float* __restrict__ w, const void* __restrict__ eraw,
        int n_tok, int capacity, int nbt,
        float* __restrict__ out_w, void* __restrict__ out_idx, int idx_mode,
        float* __restrict__ out_mask) {
    __shared__ int hA[32][NEP];
    __shared__ int hB[32][NEP];
    __shared__ int s_is64, s_last, s_ovf;
    __shared__ int run[NE];
    const int t = threadIdx.x, b = blockIdx.x;
    const int warp = t >> 5, lane = t & 31;
    const unsigned lt = (1u << lane) - 1u;

    const int tok = b * EPT + t;
    const bool valid = tok < n_tok;

    // ---- eager loads ----
    int2 v32 = make_int2(0, 0);
    float2 wv = make_float2(0.f, 0.f);
    if (valid) {
        v32 = __ldg((const int2*)eraw + tok);
        wv  = __ldg((const float2*)w + tok);
    }
    ((int*)hA)[t] = 0; ((int*)hA)[t + TPB] = 0;
    ((int*)hB)[t] = 0; ((int*)hB)[t + TPB] = 0;
    if (t < 32 * NEP - 2 * TPB) { ((int*)hA)[t + 2 * TPB] = 0; ((int*)hB)[t + 2 * TPB] = 0; }
    probe_w0(eraw, lane, &s_is64);
    __syncthreads();

    int e0 = NE + lane, e1 = NE + lane;      // unique keys for invalid lanes
    if (valid) {
        if (s_is64) {
            longlong2 v = __ldg((const longlong2*)eraw + tok);
            e0 = (int)v.x & (NE - 1); e1 = (int)v.y & (NE - 1);
        } else {
            e0 = v32.x & (NE - 1); e1 = v32.y & (NE - 1);
        }
    }

    // ---- SPECULATIVE final stores (correct iff no overflow) ----
    if (valid) {
        ((float2*)out_w)[tok] = wv;
        if (idx_mode == 1) {
            ((float2*)out_idx)[tok] = make_float2((float)e0, (float)e1);
        } else if (idx_mode == 2) {
            longlong2 iv; iv.x = e0; iv.y = e1;
            ((longlong2*)out_idx)[tok] = iv;
        }
        if (out_mask) out_mask[tok] = ((wv.x + wv.y) == 0.0f) ? 1.0f : 0.0f;
    }

    // ---- histogram ----
    unsigned m0 = __match_any_sync(0xFFFFFFFFu, e0);
    unsigned m1 = __match_any_sync(0xFFFFFFFFu, e1);
    if (valid && !(m0 & lt)) hA[warp][e0] = __popc(m0);
    if (valid && !(m1 & lt)) hB[warp][e1] = __popc(m1);
    __syncthreads();

    if (t < NE) {
        int s = 0;
        #pragma unroll
        for (int ww = 0; ww < 32; ww++) s += hA[ww][t];
        g_cnt[b][t] = s;
        if (s) atomicAdd(&g_tot[t], s);
    } else if (t < 2 * NE) {
        const int e = t - NE;
        int s = 0;
        #pragma unroll
        for (int ww = 0; ww < 32; ww++) s += hB[ww][e];
        g_cnt[nbt + b][e] = s;
        if (s) atomicAdd(&g_tot[e], s);
    }
    __syncthreads();

    // ---- arrive; only the LAST block continues ----
    if (t == 0) {
        __threadfence();
        s_last = (atomicAdd(&g_done, 1) == nbt - 1);
    }
    __syncthreads();
    if (!s_last) return;
    __threadfence();                         // acquire side

    // ---- last block: overflow check ----
    if (t == 0) s_ovf = 0;
    if (t < NE) run[t] = 0;
    __syncthreads();
    if (t < NE && g_tot[t] > capacity) atomicOr(&s_ovf, 1);
    __syncthreads();

    if (s_ovf) {
        // ======== COLD PATH: exact serial sweep by this one block ========
        // Flat order = all slot-0 tile rows, then all slot-1 tile rows.
        // run[e] carries the running per-expert count across the whole sweep.
        const bool is64 = (s_is64 != 0);
        for (int pass = 0; pass < 2; pass++) {
            for (int r = 0; r < nbt; r++) {
                ((int*)hA)[t] = 0; ((int*)hA)[t + TPB] = 0;
                if (t < 32 * NEP - 2 * TPB) ((int*)hA)[t + 2 * TPB] = 0;
                __syncthreads();

                const int tk = r * EPT + t;
                const bool v = tk < n_tok;
                int e = NE + lane;
                float wv2 = 0.f;
                if (v) {
                    if (is64) e = (int)((const long long*)eraw)[tk * 2 + pass] & (NE - 1);
                    else      e = ((const int*)eraw)[tk * 2 + pass] & (NE - 1);
                    wv2 = w[tk * 2 + pass];
                }
                unsigned m = __match_any_sync(0xFFFFFFFFu, e);
                const int wr = __popc(m & lt);
                if (v && wr == 0) hA[warp][e] = __popc(m);
                __syncthreads();

                // exclusive scan down 32 warp-rows; warp owns experts warp*2+k
                #pragma unroll
                for (int k = 0; k < 2; k++) {
                    const int e2 = warp * 2 + k;
                    int vv = hA[lane][e2];
                    int x = vv;
                    #pragma unroll
                    for (int d = 1; d < 32; d <<= 1) {
                        int y = __shfl_up_sync(0xFFFFFFFFu, x, d);
                        if (lane >= d) x += y;
                    }
                    hA[lane][e2] = x - vv;
                }
                __syncthreads();

                if (v) {
                    const int rank = run[e] + hA[warp][e] + wr;
                    const float wo = (rank < capacity) ? wv2 : 0.0f;
                    ((float*)out_w)[tk * 2 + pass] = wo;
                    if (pass == 1 && out_mask) {
                        float w0 = ((float*)out_w)[tk * 2];   // written in pass 0
                        out_mask[tk] = ((w0 + wo) == 0.0f) ? 1.0f : 0.0f;
                    }
                }
                __syncthreads();
                if (t < NE) run[t] += g_cnt[(pass ? nbt : 0) + r][t];
                __syncthreads();
            }
        }
    }

    // ---- reset for next graph replay ----
    if (t < NE) g_tot[t] = 0;
    if (t == 0) g_done = 0;
}

extern "C" void kernel_launch(void* const* d_in, const int* in_sizes, int n_in,
                              void* d_out, int out_size) {
    const float* w    = (const float*)d_in[0];
    const void*  eidx = d_in[1];

    int flat  = in_sizes[0];                 // N * TOP_K
    int n_tok = flat / 2;
    int capacity = (flat * 5 + 255) / 256;   // ceil(1.25 * flat / 64)
    if (capacity < 1) capacity = 1;
    int nbt = (n_tok + EPT - 1) / EPT;
    if (2 * nbt > MAXROWS) nbt = MAXROWS / 2;   // guard (not hit at these sizes)

    float* out = (float*)d_out;
    float* out_w    = out;
    void*  out_idx  = nullptr;
    float* out_mask = nullptr;
    int idx_mode = 0;

    if (out_size >= 3 * flat + n_tok) {          // weights + i64 indices + mask
        idx_mode = 2; out_idx = out + flat; out_mask = out + 3 * flat;
    } else if (out_size >= 2 * flat + n_tok) {   // weights + 1-word indices + mask
        idx_mode = 1; out_idx = out + flat; out_mask = out + 2 * flat;
    } else if (out_size >= flat + n_tok) {       // weights + mask
        out_mask = out + flat;
    }

    k_fused<<<nbt, TPB>>>(w, eidx, n_tok, capacity, nbt,
                          out_w, out_idx, idx_mode, out_mask);
}

// round 16
// speedup vs baseline: 1.0269x; 1.0269x over previous
#include <cuda_runtime.h>
#include <cuda_bf16.h>
#include <cstdint>

// ExpertCapacityBuffer: N tokens, TOP_K=2, 64 experts.
// capacity = ceil(1.25*N*2/64). Flat slot-major: f = slot*N + tok.
// rank(f) = #{g<f : expert(g)==expert(f)}; keep iff rank < capacity.
//
// Overflow shortcut: expert e drops anything iff total(e) > capacity.
// No grid barrier: each block writes speculative-final outputs + histogram
// + padded totals, then exits. LAST-arriving block checks totals; overflow
// (cold) -> it alone re-sweeps all tiles in flat order exactly.
// g_tot is padded to one 128B line per expert to avoid LTS atomic
// serialization (all 16K atomics previously hit 2 cache lines).

#define NE   64
#define NEP  65              // padded row kills smem bank conflicts
#define TPB  1024
#define EPT  1024
#define MAXROWS 4096
#define TSTRIDE 32           // ints per expert slot (128B line)

__device__ int g_cnt[MAXROWS][NE];
__device__ int g_tot[NE * TSTRIDE];   // zero at start; reset by last block
__device__ int g_done = 0;

// warp-0 dtype probe: int64 values <64 => odd 32-bit words of first 256B zero.
__device__ __forceinline__ void probe_w0(const void* eraw, int lane, int* s_is64) {
    if (threadIdx.x < 32) {
        unsigned x = ((const unsigned*)eraw)[2 * lane + 1];
        unsigned nz = __ballot_sync(0xFFFFFFFFu, x != 0u);
        if (lane == 0) *s_is64 = (nz == 0u);
    }
}

__global__ void __launch_bounds__(TPB, 1)
k_fused(const float* __restrict__ w, const void* __restrict__ eraw,
        int n_tok, int capacity, int nbt,
        float* __restrict__ out_w, void* __restrict__ out_idx, int idx_mode,
        float* __restrict__ out_mask) {
    __shared__ int hA[32][NEP];
    __shared__ int hB[32][NEP];
    __shared__ int s_is64, s_last, s_ovf;
    __shared__ int run[NE];
    const int t = threadIdx.x, b = blockIdx.x;
    const int warp = t >> 5, lane = t & 31;
    const unsigned lt = (1u << lane) - 1u;

    const int tok = b * EPT + t;
    const bool valid = tok < n_tok;

    // ---- eager loads ----
    int2 v32 = make_int2(0, 0);
    float2 wv = make_float2(0.f, 0.f);
    if (valid) {
        v32 = __ldg((const int2*)eraw + tok);
        wv  = __ldg((const float2*)w + tok);
    }
    ((int*)hA)[t] = 0; ((int*)hA)[t + TPB] = 0;
    ((int*)hB)[t] = 0; ((int*)hB)[t + TPB] = 0;
    if (t < 32 * NEP - 2 * TPB) { ((int*)hA)[t + 2 * TPB] = 0; ((int*)hB)[t + 2 * TPB] = 0; }
    probe_w0(eraw, lane, &s_is64);
    __syncthreads();

    int e0 = NE + lane, e1 = NE + lane;      // unique keys for invalid lanes
    if (valid) {
        if (s_is64) {
            longlong2 v = __ldg((const longlong2*)eraw + tok);
            e0 = (int)v.x & (NE - 1); e1 = (int)v.y & (NE - 1);
        } else {
            e0 = v32.x & (NE - 1); e1 = v32.y & (NE - 1);
        }
    }

    // ---- SPECULATIVE final stores (correct iff no overflow) ----
    if (valid) {
        ((float2*)out_w)[tok] = wv;
        if (idx_mode == 1) {
            ((float2*)out_idx)[tok] = make_float2((float)e0, (float)e1);
        } else if (idx_mode == 2) {
            longlong2 iv; iv.x = e0; iv.y = e1;
            ((longlong2*)out_idx)[tok] = iv;
        }
        if (out_mask) out_mask[tok] = ((wv.x + wv.y) == 0.0f) ? 1.0f : 0.0f;
    }

    // ---- histogram ----
    unsigned m0 = __match_any_sync(0xFFFFFFFFu, e0);
    unsigned m1 = __match_any_sync(0xFFFFFFFFu, e1);
    if (valid && !(m0 & lt)) hA[warp][e0] = __popc(m0);
    if (valid && !(m1 & lt)) hB[warp][e1] = __popc(m1);
    __syncthreads();

    if (t < NE) {
        int s = 0;
        #pragma unroll
        for (int ww = 0; ww < 32; ww++) s += hA[ww][t];
        g_cnt[b][t] = s;
        if (s) atomicAdd(&g_tot[t * TSTRIDE], s);          // padded: 1 line/expert
    } else if (t < 2 * NE) {
        const int e = t - NE;
        int s = 0;
        #pragma unroll
        for (int ww = 0; ww < 32; ww++) s += hB[ww][e];
        g_cnt[nbt + b][e] = s;
        if (s) atomicAdd(&g_tot[e * TSTRIDE], s);
    }
    __syncthreads();

    // ---- arrive; only the LAST block continues ----
    if (t == 0) {
        __threadfence();
        s_last = (atomicAdd(&g_done, 1) == nbt - 1);
    }
    __syncthreads();
    if (!s_last) return;
    __threadfence();                         // acquire side

    // ---- last block: overflow check ----
    if (t == 0) s_ovf = 0;
    if (t < NE) run[t] = 0;
    __syncthreads();
    if (t < NE && g_tot[t * TSTRIDE] > capacity) atomicOr(&s_ovf, 1);
    __syncthreads();

    if (s_ovf) {
        // ======== COLD PATH: exact serial sweep by this one block ========
        const bool is64 = (s_is64 != 0);
        for (int pass = 0; pass < 2; pass++) {
            for (int r = 0; r < nbt; r++) {
                ((int*)hA)[t] = 0; ((int*)hA)[t + TPB] = 0;
                if (t < 32 * NEP - 2 * TPB) ((int*)hA)[t + 2 * TPB] = 0;
                __syncthreads();

                const int tk = r * EPT + t;
                const bool v = tk < n_tok;
                int e = NE + lane;
                float wv2 = 0.f;
                if (v) {
                    if (is64) e = (int)((const long long*)eraw)[tk * 2 + pass] & (NE - 1);
                    else      e = ((const int*)eraw)[tk * 2 + pass] & (NE - 1);
                    wv2 = w[tk * 2 + pass];
                }
                unsigned m = __match_any_sync(0xFFFFFFFFu, e);
                const int wr = __popc(m & lt);
                if (v && wr == 0) hA[warp][e] = __popc(m);
                __syncthreads();

                #pragma unroll
                for (int k = 0; k < 2; k++) {
                    const int e2 = warp * 2 + k;
                    int vv = hA[lane][e2];
                    int x = vv;
                    #pragma unroll
                    for (int d = 1; d < 32; d <<= 1) {
                        int y = __shfl_up_sync(0xFFFFFFFFu, x, d);
                        if (lane >= d) x += y;
                    }
                    hA[lane][e2] = x - vv;
                }
                __syncthreads();

                if (v) {
                    const int rank = run[e] + hA[warp][e] + wr;
                    const float wo = (rank < capacity) ? wv2 : 0.0f;
                    ((float*)out_w)[tk * 2 + pass] = wo;
                    if (pass == 1 && out_mask) {
                        float w0 = ((float*)out_w)[tk * 2];   // written in pass 0
                        out_mask[tk] = ((w0 + wo) == 0.0f) ? 1.0f : 0.0f;
                    }
                }
                __syncthreads();
                if (t < NE) run[t] += g_cnt[(pass ? nbt : 0) + r][t];
                __syncthreads();
            }
        }
    }

    // ---- reset for next graph replay ----
    if (t < NE) g_tot[t * TSTRIDE] = 0;
    if (t == 0) g_done = 0;
}

extern "C" void kernel_launch(void* const* d_in, const int* in_sizes, int n_in,
                              void* d_out, int out_size) {
    const float* w    = (const float*)d_in[0];
    const void*  eidx = d_in[1];

    int flat  = in_sizes[0];                 // N * TOP_K
    int n_tok = flat / 2;
    int capacity = (flat * 5 + 255) / 256;   // ceil(1.25 * flat / 64)
    if (capacity < 1) capacity = 1;
    int nbt = (n_tok + EPT - 1) / EPT;
    if (2 * nbt > MAXROWS) nbt = MAXROWS / 2;   // guard (not hit at these sizes)

    float* out = (float*)d_out;
    float* out_w    = out;
    void*  out_idx  = nullptr;
    float* out_mask = nullptr;
    int idx_mode = 0;

    if (out_size >= 3 * flat + n_tok) {          // weights + i64 indices + mask
        idx_mode = 2; out_idx = out + flat; out_mask = out + 3 * flat;
    } else if (out_size >= 2 * flat + n_tok) {   // weights + 1-word indices + mask
        idx_mode = 1; out_idx = out + flat; out_mask = out + 2 * flat;
    } else if (out_size >= flat + n_tok) {       // weights + mask
        out_mask = out + flat;
    }

    k_fused<<<nbt, TPB>>>(w, eidx, n_tok, capacity, nbt,
                          out_w, out_idx, idx_mode, out_mask);
}